// round 1
// baseline (speedup 1.0000x reference)
#include <cuda_runtime.h>

// Problem constants (fixed by setup_inputs; nfrag input = 7 by construction)
#define L_Q   1024
#define B_Q   64
#define D_Q   512
#define U_Q   20
#define LTOT  3072                 // 3*L
#define NFRAG 7
#define FLEN  439                  // ceil(3072/7); 7*439 = 3073, pad = 1
#define NCH   (NFRAG * B_Q)        // 448 independent scan chains

// Scratch (no allocations allowed -> __device__ globals)
__device__ float g_c[FLEN * NCH * 3];                    // c_tilde, scan layout [l][chain][3]
__device__ float g_coords[(NFRAG * FLEN) * B_Q * 3];     // raw fragment coords [(f*FLEN+l)][b][3]
__device__ float g_Mt[NFRAG * B_Q * 12];                 // per (frag,b): 3x3 M row-major + t

// ---------- packed fp32 (Blackwell FFMA2) helpers ----------
static __device__ __forceinline__ unsigned long long dup2(float v) {
    unsigned long long r;
    asm("mov.b64 %0, {%1, %1};" : "=l"(r) : "f"(v));
    return r;
}
static __device__ __forceinline__ unsigned long long fma2(unsigned long long a,
                                                          unsigned long long b,
                                                          unsigned long long c) {
    unsigned long long d;
    asm("fma.rn.f32x2 %0, %1, %2, %3;" : "=l"(d) : "l"(a), "l"(b), "l"(c));
    return d;
}
static __device__ __forceinline__ float2 unpk(unsigned long long v) {
    float2 r;
    asm("mov.b64 {%0, %1}, %2;" : "=f"(r.x), "=f"(r.y) : "l"(v));
    return r;
}

// =====================================================================
// Kernel 1: logits GEMM (65536 x 512 x 20) + softmax + angularization +
//           torsion_to_srf, writing c_tilde in scan-friendly layout.
// 4 rows/thread, outputs paired (u,u+1) so W loads are LDS.64 = the packed
// FFMA2 multiplier directly (no pack cost for W).
// =====================================================================
__global__ __launch_bounds__(128) void k_gemm(
    const float* __restrict__ inp, const float* __restrict__ W,
    const float* __restrict__ bias, const float* __restrict__ alpha,
    const float* __restrict__ bl, const float* __restrict__ ba)
{
    __shared__ __align__(16) float sW[D_Q * U_Q];        // [k][u], 40 KB
    __shared__ float sSin[U_Q * 3], sCos[U_Q * 3], sB[U_Q];
    int tid = threadIdx.x;

    for (int idx = tid; idx < D_Q * U_Q; idx += 128) {
        int u = idx >> 9, k = idx & (D_Q - 1);           // idx = u*512 + k
        sW[k * U_Q + u] = W[idx];
    }
    if (tid < U_Q * 3) { float a = alpha[tid]; sSin[tid] = sinf(a); sCos[tid] = cosf(a); }
    if (tid < U_Q) sB[tid] = bias[tid];

    // pNeRF pad element (global position 3072 -> frag 6, step 438), value 0.1
    if (blockIdx.x == 0 && tid < B_Q) {
        float* p = &g_c[((size_t)(FLEN - 1) * NCH + 6 * B_Q + tid) * 3];
        p[0] = 0.1f; p[1] = 0.1f; p[2] = 0.1f;
    }
    __syncthreads();

    float rc[3], rs[3];
#pragma unroll
    for (int j = 0; j < 3; j++) { float r = bl[j], t = ba[j]; rc[j] = r * cosf(t); rs[j] = r * sinf(t); }

    int gid = blockIdx.x * 128 + tid;
    int r0  = gid * 4;                                   // 4 consecutive rows per thread
    const float* P = inp + (size_t)r0 * D_Q;

    unsigned long long acc[4][10];                       // 4 rows x 10 u-pairs
#pragma unroll
    for (int r = 0; r < 4; r++)
#pragma unroll
        for (int p = 0; p < 10; p++) acc[r][p] = 0ull;   // bits of (0.f,0.f)

    for (int k4 = 0; k4 < D_Q / 4; ++k4) {
        float4 a0 = *(const float4*)(P + k4 * 4);
        float4 a1 = *(const float4*)(P + D_Q + k4 * 4);
        float4 a2 = *(const float4*)(P + 2 * D_Q + k4 * 4);
        float4 a3 = *(const float4*)(P + 3 * D_Q + k4 * 4);
#pragma unroll
        for (int kk = 0; kk < 4; ++kk) {
            const unsigned long long* wr =
                (const unsigned long long*)(sW + (k4 * 4 + kk) * U_Q);
            unsigned long long v0 = dup2(((const float*)&a0)[kk]);
            unsigned long long v1 = dup2(((const float*)&a1)[kk]);
            unsigned long long v2 = dup2(((const float*)&a2)[kk]);
            unsigned long long v3 = dup2(((const float*)&a3)[kk]);
#pragma unroll
            for (int p = 0; p < 10; p++) {
                unsigned long long w = wr[p];            // LDS.64 broadcast: (w_{2p}, w_{2p+1})
                acc[0][p] = fma2(v0, w, acc[0][p]);
                acc[1][p] = fma2(v1, w, acc[1][p]);
                acc[2][p] = fma2(v2, w, acc[2][p]);
                acc[3][p] = fma2(v3, w, acc[3][p]);
            }
        }
    }

#pragma unroll
    for (int r = 0; r < 4; r++) {
        float lg[U_Q];
#pragma unroll
        for (int p = 0; p < 10; p++) { float2 t = unpk(acc[r][p]); lg[2*p] = t.x; lg[2*p+1] = t.y; }
        float mx = -1e30f;
#pragma unroll
        for (int u = 0; u < U_Q; u++) { lg[u] += sB[u]; mx = fmaxf(mx, lg[u]); }
        // softmax numerator only: phi = atan2(s,c); cos/sin(phi) via s,c ratio so
        // the 1/sum(exp) normalization cancels -> no division, no trig.
        float sj[3] = {0.f,0.f,0.f}, cj[3] = {0.f,0.f,0.f};
#pragma unroll
        for (int u = 0; u < U_Q; u++) {
            float e = __expf(lg[u] - mx);
#pragma unroll
            for (int j = 0; j < 3; j++) {
                sj[j] = fmaf(e, sSin[u*3+j], sj[j]);
                cj[j] = fmaf(e, sCos[u*3+j], cj[j]);
            }
        }
        int row = r0 + r;
        int l = row >> 6, b = row & 63;
#pragma unroll
        for (int j = 0; j < 3; j++) {
            float s = sj[j], c = cj[j];
            float rn = rsqrtf(fmaf(s, s, c * c));
            int m  = 3 * l + j;
            int f  = m / FLEN;
            int ls = m - f * FLEN;
            float* p = &g_c[((size_t)ls * NCH + f * B_Q + b) * 3];
            p[0] = rc[j];
            p[1] = rs[j] * (c * rn);                     // r*sin(theta)*cos(phi)
            p[2] = rs[j] * (s * rn);                     // r*sin(theta)*sin(phi)
        }
    }
}

// =====================================================================
// Kernel 2: pNeRF serial scan. 448 chains, 8 chains/block, c_tilde staged
// fully in static shared (42 KB) so the serial loop is SMEM-latency only.
// n = normalize(cross(AB,BC)) is independent of bc's normalization, which
// takes one rsqrt off the critical path.
// =====================================================================
__global__ __launch_bounds__(64) void k_scan()
{
    __shared__ float sc[(FLEN + 1) * 24];                // +1 row: prefetch overrun pad
    int tid = threadIdx.x;
    int chain0 = blockIdx.x * 8;
    for (int idx = tid; idx < FLEN * 24; idx += 64) {
        int l = idx / 24;
        int r = idx - l * 24;
        sc[idx] = g_c[(size_t)l * (NCH * 3) + chain0 * 3 + r];
    }
    __syncthreads();
    if (tid >= 8) return;
    int chain = chain0 + tid;
    int f = chain >> 6, b = chain & 63;

    float Ax = -0.7071067811865476f, Ay = 1.224744871391589f,  Az = 0.0f;
    float Bx = -1.4142135623730951f, By = 0.0f,                Bz = 0.0f;
    float Cx = 0.0f,                 Cy = 0.0f,                Cz = 0.0f;

    float* outp = &g_coords[(((size_t)f * FLEN) * B_Q + b) * 3];
    const float* cp = sc + tid * 3;
    float n0 = cp[0], n1 = cp[1], n2 = cp[2];
    for (int l = 0; l < FLEN; ++l) {
        float c0 = n0, c1 = n1, c2 = n2;
        cp += 24;
        n0 = cp[0]; n1 = cp[1]; n2 = cp[2];              // prefetch next step

        float bx = Cx - Bx, by = Cy - By, bz = Cz - Bz;  // BC (unnormalized)
        float ax = Bx - Ax, ay = By - Ay, az = Bz - Az;  // AB
        float Nx = fmaf(ay, bz, -az * by);               // cross(AB, BC)
        float Ny = fmaf(az, bx, -ax * bz);
        float Nz = fmaf(ax, by, -ay * bx);
        float d1 = fmaf(bx, bx, fmaf(by, by, bz * bz));
        float d2 = fmaf(Nx, Nx, fmaf(Ny, Ny, Nz * Nz));
        float s1 = rsqrtf(d1);
        float s2 = rsqrtf(d2);
        float mxv = fmaf(Ny, bz, -Nz * by);              // cross(N, BC)
        float myv = fmaf(Nz, bx, -Nx * bz);
        float mzv = fmaf(Nx, by, -Ny * bx);
        float u0 = c0 * s1;
        float u1 = c1 * (s1 * s2);
        float u2 = c2 * s2;
        float Dx = fmaf(u1, mxv, fmaf(u2, Nx, fmaf(u0, bx, Cx)));
        float Dy = fmaf(u1, myv, fmaf(u2, Ny, fmaf(u0, by, Cy)));
        float Dz = fmaf(u1, mzv, fmaf(u2, Nz, fmaf(u0, bz, Cz)));

        float* o = outp + (size_t)l * (B_Q * 3);
        o[0] = Dx; o[1] = Dy; o[2] = Dz;

        Ax = Bx; Ay = By; Az = Bz;
        Bx = Cx; By = Cy; Bz = Cz;
        Cx = Dx; Cy = Dy; Cz = Dz;
    }
}

// =====================================================================
// Kernel 3a: per-batch cumulative fragment transforms.
// Fragment j final transform: M_j = R_0...R_{j-1}, t_j = M_{j-1}C_{j-1}+t_{j-1}
// (exactly the reference's sequential realignment, composed).
// =====================================================================
__global__ void k_align()
{
    int b = threadIdx.x;
    if (b >= B_Q) return;
    float M00=1.f,M01=0.f,M02=0.f,M10=0.f,M11=1.f,M12=0.f,M20=0.f,M21=0.f,M22=1.f;
    float tx=0.f,ty=0.f,tz=0.f;
    {
        float* mt = &g_Mt[(size_t)b * 12];
        mt[0]=1.f;mt[1]=0.f;mt[2]=0.f;mt[3]=0.f;mt[4]=1.f;mt[5]=0.f;
        mt[6]=0.f;mt[7]=0.f;mt[8]=1.f;mt[9]=0.f;mt[10]=0.f;mt[11]=0.f;
    }
    for (int j = 0; j < NFRAG - 1; ++j) {
        const float* A = &g_coords[(((size_t)j * FLEN + (FLEN - 3)) * B_Q + b) * 3];
        const float* Bv = A + B_Q * 3;
        const float* Cv = Bv + B_Q * 3;
        float bx=Cv[0]-Bv[0], by=Cv[1]-Bv[1], bz=Cv[2]-Bv[2];
        float ax=Bv[0]-A[0],  ay=Bv[1]-A[1],  az=Bv[2]-A[2];
        float Nx=fmaf(ay,bz,-az*by), Ny=fmaf(az,bx,-ax*bz), Nz=fmaf(ax,by,-ay*bx);
        float s1=rsqrtf(fmaf(bx,bx,fmaf(by,by,bz*bz)));
        float s2=rsqrtf(fmaf(Nx,Nx,fmaf(Ny,Ny,Nz*Nz)));
        float s12=s1*s2;
        float mxv=fmaf(Ny,bz,-Nz*by)*s12;
        float myv=fmaf(Nz,bx,-Nx*bz)*s12;
        float mzv=fmaf(Nx,by,-Ny*bx)*s12;
        float bcx=bx*s1, bcy=by*s1, bcz=bz*s1;
        float nx=Nx*s2,  ny=Ny*s2,  nz=Nz*s2;
        // R columns [bc, m, n]; Mnew = M * R
        float N00 = M00*bcx + M01*bcy + M02*bcz;
        float N10 = M10*bcx + M11*bcy + M12*bcz;
        float N20 = M20*bcx + M21*bcy + M22*bcz;
        float N01 = M00*mxv + M01*myv + M02*mzv;
        float N11 = M10*mxv + M11*myv + M12*mzv;
        float N21 = M20*mxv + M21*myv + M22*mzv;
        float N02 = M00*nx + M01*ny + M02*nz;
        float N12 = M10*nx + M11*ny + M12*nz;
        float N22 = M20*nx + M21*ny + M22*nz;
        float ntx = tx + M00*Cv[0] + M01*Cv[1] + M02*Cv[2];
        float nty = ty + M10*Cv[0] + M11*Cv[1] + M12*Cv[2];
        float ntz = tz + M20*Cv[0] + M21*Cv[1] + M22*Cv[2];
        M00=N00;M01=N01;M02=N02;M10=N10;M11=N11;M12=N12;M20=N20;M21=N21;M22=N22;
        tx=ntx;ty=nty;tz=ntz;
        float* mt = &g_Mt[((size_t)(j + 1) * B_Q + b) * 12];
        mt[0]=M00;mt[1]=M01;mt[2]=M02;mt[3]=M10;mt[4]=M11;mt[5]=M12;
        mt[6]=M20;mt[7]=M21;mt[8]=M22;mt[9]=tx;mt[10]=ty;mt[11]=tz;
    }
}

// =====================================================================
// Kernel 3b: apply per-fragment affine transform, write final output.
// =====================================================================
__global__ __launch_bounds__(256) void k_out(float* __restrict__ out)
{
    int tid = blockIdx.x * 256 + threadIdx.x;
    if (tid >= LTOT * B_Q) return;
    int m = tid >> 6, b = tid & 63;
    int f = m / FLEN;
    const float* x = &g_coords[((size_t)m * B_Q + b) * 3];
    const float* M = &g_Mt[((size_t)f * B_Q + b) * 12];
    float X = x[0], Y = x[1], Z = x[2];
    float ox = fmaf(M[0], X, fmaf(M[1], Y, fmaf(M[2], Z, M[9])));
    float oy = fmaf(M[3], X, fmaf(M[4], Y, fmaf(M[5], Z, M[10])));
    float oz = fmaf(M[6], X, fmaf(M[7], Y, fmaf(M[8], Z, M[11])));
    float* o = out + (size_t)tid * 3;
    o[0] = ox; o[1] = oy; o[2] = oz;
}

extern "C" void kernel_launch(void* const* d_in, const int* in_sizes, int n_in,
                              void* d_out, int out_size)
{
    (void)in_sizes; (void)n_in; (void)out_size;
    const float* inp   = (const float*)d_in[0];
    const float* W     = (const float*)d_in[1];
    const float* bias  = (const float*)d_in[2];
    const float* alpha = (const float*)d_in[3];
    const float* bl    = (const float*)d_in[4];
    const float* ba    = (const float*)d_in[5];
    // d_in[6] = nfrag (== 7 by construction; compile-time constant here)

    k_gemm <<<128, 128>>>(inp, W, bias, alpha, bl, ba);   // 16384 thr * 4 rows = 65536
    k_scan <<<56, 64>>>();                                // 448 chains / 8 per block
    k_align<<<1, 64>>>();
    k_out  <<<(LTOT * B_Q + 255) / 256, 256>>>((float*)d_out);
}

// round 3
// speedup vs baseline: 1.2409x; 1.2409x over previous
#include <cuda_runtime.h>

#define L_Q   1024
#define B_Q   64
#define D_Q   512
#define U_Q   20
#define LTOT  3072                 // 3*L
#define NFRAG 7
#define FLEN  439                  // ceil(3072/7); 7*439 = 3073, pad = 1
#define NCH   (NFRAG * B_Q)        // 448 independent scan chains
#define SCAN_CHB 8                 // chains per scan block (static smem 28.2 KB)

// Scratch (no allocations allowed -> __device__ globals)
__device__ float2 g_c2[FLEN * NCH];                      // (c1, c2) per step, [ls][chain]
__device__ float  g_coords[(NFRAG * FLEN) * B_Q * 3];    // raw fragment coords [(f*FLEN+l)][b][3]
__device__ float4 g_Mt4[NFRAG * B_Q * 3];                // per (frag,b): [M00 M01 M02 M10][M11 M12 M20 M21][M22 tx ty tz]

// ---------- packed fp32 (Blackwell FFMA2) helpers ----------
static __device__ __forceinline__ unsigned long long dup2(float v) {
    unsigned long long r;
    asm("mov.b64 %0, {%1, %1};" : "=l"(r) : "f"(v));
    return r;
}
static __device__ __forceinline__ unsigned long long fma2(unsigned long long a,
                                                          unsigned long long b,
                                                          unsigned long long c) {
    unsigned long long d;
    asm("fma.rn.f32x2 %0, %1, %2, %3;" : "=l"(d) : "l"(a), "l"(b), "l"(c));
    return d;
}
static __device__ __forceinline__ float2 unpk(unsigned long long v) {
    float2 r;
    asm("mov.b64 {%0, %1}, %2;" : "=f"(r.x), "=f"(r.y) : "l"(v));
    return r;
}

// =====================================================================
// Kernel 1: logits GEMM (65536 x 512 x 20) + softmax-free angularization.
// 2 rows/thread -> 1024 warps (~7/SM) so the FFMA2 pipe stays fed.
// Epilogue stores (c1, c2) = (rs*cos(phi), rs*sin(phi)); c0 = rc is a
// per-bond constant consumed directly by the scan.
// =====================================================================
__global__ __launch_bounds__(128) void k_gemm(
    const float* __restrict__ inp, const float* __restrict__ W,
    const float* __restrict__ bias, const float* __restrict__ alpha,
    const float* __restrict__ bl, const float* __restrict__ ba)
{
    __shared__ __align__(16) float sW[D_Q * U_Q];        // [k][u], 40 KB
    __shared__ float sSin[U_Q * 3], sCos[U_Q * 3], sB[U_Q];
    int tid = threadIdx.x;

    for (int idx = tid; idx < D_Q * U_Q; idx += 128) {
        int u = idx >> 9, k = idx & (D_Q - 1);           // idx = u*512 + k
        sW[k * U_Q + u] = W[idx];
    }
    if (tid < U_Q * 3) { float a = alpha[tid]; sSin[tid] = sinf(a); sCos[tid] = cosf(a); }
    if (tid < U_Q) sB[tid] = bias[tid];

    // pNeRF pad element (global position 3072 -> frag 6, step ls=438).
    // Last step of last fragment: its output row is dropped and its frame is
    // never consumed, so only finite values matter.
    if (blockIdx.x == 0 && tid < B_Q) {
        g_c2[(FLEN - 1) * NCH + 6 * B_Q + tid] = make_float2(0.1f, 0.1f);
    }
    __syncthreads();

    float rs[3];
#pragma unroll
    for (int j = 0; j < 3; j++) rs[j] = bl[j] * sinf(ba[j]);

    int gid = blockIdx.x * 128 + tid;
    int r0  = gid * 2;                                   // 2 consecutive rows per thread
    const float* P = inp + (size_t)r0 * D_Q;

    unsigned long long acc[2][10];
#pragma unroll
    for (int r = 0; r < 2; r++)
#pragma unroll
        for (int p = 0; p < 10; p++) acc[r][p] = 0ull;

    for (int k4 = 0; k4 < D_Q / 4; ++k4) {
        float4 a0 = *(const float4*)(P + k4 * 4);
        float4 a1 = *(const float4*)(P + D_Q + k4 * 4);
#pragma unroll
        for (int kk = 0; kk < 4; ++kk) {
            const unsigned long long* wr =
                (const unsigned long long*)(sW + (k4 * 4 + kk) * U_Q);
            unsigned long long v0 = dup2(((const float*)&a0)[kk]);
            unsigned long long v1 = dup2(((const float*)&a1)[kk]);
#pragma unroll
            for (int p = 0; p < 10; p++) {
                unsigned long long w = wr[p];            // LDS.64 broadcast
                acc[0][p] = fma2(v0, w, acc[0][p]);
                acc[1][p] = fma2(v1, w, acc[1][p]);
            }
        }
    }

#pragma unroll
    for (int r = 0; r < 2; r++) {
        float lg[U_Q];
#pragma unroll
        for (int p = 0; p < 10; p++) { float2 t = unpk(acc[r][p]); lg[2*p] = t.x; lg[2*p+1] = t.y; }
        float mx = -1e30f;
#pragma unroll
        for (int u = 0; u < U_Q; u++) { lg[u] += sB[u]; mx = fmaxf(mx, lg[u]); }
        // softmax numerator only: phi = atan2(s,c); cos/sin(phi) from (s,c)
        // ratio, so the softmax normalization cancels.
        float sj[3] = {0.f,0.f,0.f}, cj[3] = {0.f,0.f,0.f};
#pragma unroll
        for (int u = 0; u < U_Q; u++) {
            float e = __expf(lg[u] - mx);
#pragma unroll
            for (int j = 0; j < 3; j++) {
                sj[j] = fmaf(e, sSin[u*3+j], sj[j]);
                cj[j] = fmaf(e, sCos[u*3+j], cj[j]);
            }
        }
        int row = r0 + r;
        int l = row >> 6, b = row & 63;
#pragma unroll
        for (int j = 0; j < 3; j++) {
            float s = sj[j], c = cj[j];
            float rn = rsqrtf(fmaf(s, s, c * c));
            int m  = 3 * l + j;
            int f  = m / FLEN;
            int ls = m - f * FLEN;
            g_c2[ls * NCH + f * B_Q + b] =
                make_float2(rs[j] * (c * rn), rs[j] * (s * rn));
        }
    }
}

// =====================================================================
// Kernel 2: pNeRF scan, unit-frame recurrence with Newton-corrected
// normalization (stable: correction error is squared each step).
//   disp = rc_j*bc + c1*mh + c2*n            (frame is unit)
//   N    = cross(bc, disp);  |N|^2 ~= rs_j^2 (analytic Newton seed)
//   s    = x0*(1.5 - 0.5*d2*x0^2), x0 = 1/rs_j   -> n = N*s  (honest norm)
//   bc'  = disp * (1/r_j)                    (analytic, contractive)
//   mh'  = cross(n, bc')
// Bond type of local step l in fragment f is (f + l) % 3 (439 % 3 == 1),
// handled by unroll-by-3 with pre-rotated per-bond constants.
// =====================================================================
__global__ __launch_bounds__(64) void k_scan(const float* __restrict__ bl,
                                             const float* __restrict__ ba)
{
    __shared__ float2 sc[(FLEN + 2) * SCAN_CHB];         // 28.2 KB static
    int tid = threadIdx.x;
    int chain0 = blockIdx.x * SCAN_CHB;
    for (int idx = tid; idx < (FLEN + 2) * SCAN_CHB; idx += 64) {
        int lsr = idx >> 3;
        int lane = idx & 7;
        sc[idx] = (lsr < FLEN) ? g_c2[lsr * NCH + chain0 + lane]
                               : make_float2(0.f, 0.f);
    }
    __syncthreads();
    if (tid >= SCAN_CHB) return;
    int chain = chain0 + tid;
    int f = chain >> 6, b = chain & 63;
    int ph = f % 3;

    float rcA[3], irA[3], nA[3], nB[3];
#pragma unroll
    for (int k = 0; k < 3; k++) {
        int j = ph + k; if (j >= 3) j -= 3;
        float r = bl[j], t = ba[j];
        rcA[k] = r * cosf(t);
        irA[k] = 1.f / r;
        float x0 = 1.f / (r * sinf(t));
        nA[k] = 1.5f * x0;
        nB[k] = 0.5f * x0 * x0 * x0;
    }

    // init frame from A0,B0,C0 (already unit after reference normalization)
    float bcx = 1.f, bcy = 0.f, bcz = 0.f;
    float nx  = 0.f, ny  = 0.f, nz  = 1.f;
    float mhx = 0.f, mhy = 1.f, mhz = 0.f;
    float Cx = 0.f, Cy = 0.f, Cz = 0.f;

    float* outp = &g_coords[(((size_t)f * FLEN) * B_Q + b) * 3];
    const float2* pp = sc + tid;
    int l = 0;

#define SCAN_STEP(k)                                                         \
    {                                                                        \
        float2 cc = pp[l * SCAN_CHB];                                        \
        float dx = fmaf(cc.x, mhx, fmaf(cc.y, nx, rcA[k] * bcx));            \
        float dy = fmaf(cc.x, mhy, fmaf(cc.y, ny, rcA[k] * bcy));            \
        float dz = fmaf(cc.x, mhz, fmaf(cc.y, nz, rcA[k] * bcz));            \
        float Nx = fmaf(bcy, dz, -(bcz * dy));                               \
        float Ny = fmaf(bcz, dx, -(bcx * dz));                               \
        float Nz = fmaf(bcx, dy, -(bcy * dx));                               \
        float d2 = fmaf(Nx, Nx, fmaf(Ny, Ny, Nz * Nz));                      \
        float sfac = fmaf(d2, -nB[k], nA[k]);                                \
        nx = Nx * sfac; ny = Ny * sfac; nz = Nz * sfac;                      \
        bcx = dx * irA[k]; bcy = dy * irA[k]; bcz = dz * irA[k];             \
        mhx = fmaf(ny, bcz, -(nz * bcy));                                    \
        mhy = fmaf(nz, bcx, -(nx * bcz));                                    \
        mhz = fmaf(nx, bcy, -(ny * bcx));                                    \
        Cx += dx; Cy += dy; Cz += dz;                                        \
        float* o = outp + (size_t)l * (B_Q * 3);                             \
        o[0] = Cx; o[1] = Cy; o[2] = Cz;                                     \
        ++l;                                                                 \
    }

    for (int it = 0; it < 146; ++it) { SCAN_STEP(0) SCAN_STEP(1) SCAN_STEP(2) }
    SCAN_STEP(0)                                         // 439 = 3*146 + 1
#undef SCAN_STEP
}

// =====================================================================
// Kernel 3a: per-batch cumulative fragment transforms (composed affine).
// Frag j gets M_j = R_0...R_{j-1}, t_j = t_{j-1} + M_{j-1} C_{j-1}.
// =====================================================================
__global__ void k_align()
{
    int b = threadIdx.x;
    if (b >= B_Q) return;
    float M00=1.f,M01=0.f,M02=0.f,M10=0.f,M11=1.f,M12=0.f,M20=0.f,M21=0.f,M22=1.f;
    float tx=0.f,ty=0.f,tz=0.f;
    {
        float4* mt = &g_Mt4[(size_t)b * 3];
        mt[0] = make_float4(1.f,0.f,0.f,0.f);
        mt[1] = make_float4(1.f,0.f,0.f,0.f);
        mt[2] = make_float4(1.f,0.f,0.f,0.f);
    }
    for (int j = 0; j < NFRAG - 1; ++j) {
        const float* A = &g_coords[(((size_t)j * FLEN + (FLEN - 3)) * B_Q + b) * 3];
        const float* Bv = A + B_Q * 3;
        const float* Cv = Bv + B_Q * 3;
        float bx=Cv[0]-Bv[0], by=Cv[1]-Bv[1], bz=Cv[2]-Bv[2];
        float ax=Bv[0]-A[0],  ay=Bv[1]-A[1],  az=Bv[2]-A[2];
        float Nx=fmaf(ay,bz,-az*by), Ny=fmaf(az,bx,-ax*bz), Nz=fmaf(ax,by,-ay*bx);
        float s1=rsqrtf(fmaf(bx,bx,fmaf(by,by,bz*bz)));
        float s2=rsqrtf(fmaf(Nx,Nx,fmaf(Ny,Ny,Nz*Nz)));
        float s12=s1*s2;
        float mxv=fmaf(Ny,bz,-Nz*by)*s12;
        float myv=fmaf(Nz,bx,-Nx*bz)*s12;
        float mzv=fmaf(Nx,by,-Ny*bx)*s12;
        float bcx=bx*s1, bcy=by*s1, bcz=bz*s1;
        float nx=Nx*s2,  ny=Ny*s2,  nz=Nz*s2;
        float N00 = M00*bcx + M01*bcy + M02*bcz;
        float N10 = M10*bcx + M11*bcy + M12*bcz;
        float N20 = M20*bcx + M21*bcy + M22*bcz;
        float N01 = M00*mxv + M01*myv + M02*mzv;
        float N11 = M10*mxv + M11*myv + M12*mzv;
        float N21 = M20*mxv + M21*myv + M22*mzv;
        float N02 = M00*nx + M01*ny + M02*nz;
        float N12 = M10*nx + M11*ny + M12*nz;
        float N22 = M20*nx + M21*ny + M22*nz;
        float ntx = tx + M00*Cv[0] + M01*Cv[1] + M02*Cv[2];
        float nty = ty + M10*Cv[0] + M11*Cv[1] + M12*Cv[2];
        float ntz = tz + M20*Cv[0] + M21*Cv[1] + M22*Cv[2];
        M00=N00;M01=N01;M02=N02;M10=N10;M11=N11;M12=N12;M20=N20;M21=N21;M22=N22;
        tx=ntx;ty=nty;tz=ntz;
        float4* mt = &g_Mt4[((size_t)(j + 1) * B_Q + b) * 3];
        mt[0] = make_float4(M00,M01,M02,M10);
        mt[1] = make_float4(M11,M12,M20,M21);
        mt[2] = make_float4(M22,tx,ty,tz);
    }
}

// =====================================================================
// Kernel 3b: apply per-fragment affine; 4 points/thread, all float4 IO.
// =====================================================================
__global__ __launch_bounds__(256) void k_out(float* __restrict__ out)
{
    int t = blockIdx.x * 256 + threadIdx.x;              // t < 49152
    int m = t >> 4;
    int b4 = (t & 15) * 4;
    int f = m / FLEN;
    const float4* X = (const float4*)&g_coords[((size_t)m * B_Q + b4) * 3];
    float4 x0 = X[0], x1 = X[1], x2 = X[2];
    float px[4] = {x0.x, x0.w, x1.z, x2.y};
    float py[4] = {x0.y, x1.x, x1.w, x2.z};
    float pz[4] = {x0.z, x1.y, x2.x, x2.w};
    float r[12];
#pragma unroll
    for (int i = 0; i < 4; i++) {
        const float4* M = &g_Mt4[((size_t)f * B_Q + b4 + i) * 3];
        float4 m0 = M[0], m1 = M[1], m2 = M[2];
        r[i*3+0] = fmaf(m0.x, px[i], fmaf(m0.y, py[i], fmaf(m0.z, pz[i], m2.y)));
        r[i*3+1] = fmaf(m0.w, px[i], fmaf(m1.x, py[i], fmaf(m1.y, pz[i], m2.z)));
        r[i*3+2] = fmaf(m1.z, px[i], fmaf(m1.w, py[i], fmaf(m2.x, pz[i], m2.w)));
    }
    float4* O = (float4*)(out + ((size_t)m * B_Q + b4) * 3);
    O[0] = make_float4(r[0], r[1], r[2],  r[3]);
    O[1] = make_float4(r[4], r[5], r[6],  r[7]);
    O[2] = make_float4(r[8], r[9], r[10], r[11]);
}

extern "C" void kernel_launch(void* const* d_in, const int* in_sizes, int n_in,
                              void* d_out, int out_size)
{
    (void)in_sizes; (void)n_in; (void)out_size;
    const float* inp   = (const float*)d_in[0];
    const float* W     = (const float*)d_in[1];
    const float* bias  = (const float*)d_in[2];
    const float* alpha = (const float*)d_in[3];
    const float* bl    = (const float*)d_in[4];
    const float* ba    = (const float*)d_in[5];
    // d_in[6] = nfrag (== 7 by construction; compile-time constant here)

    k_gemm <<<256, 128>>>(inp, W, bias, alpha, bl, ba);   // 32768 thr * 2 rows
    k_scan <<<NCH / SCAN_CHB, 64>>>(bl, ba);              // 56 blocks * 8 chains
    k_align<<<1, 64>>>();
    k_out  <<<192, 256>>>((float*)d_out);                 // 49152 thr * 4 points
}